// round 7
// baseline (speedup 1.0000x reference)
#include <cuda_runtime.h>
#include <cstdint>

#define KB     8192          // bins (bin = S>>1, S = round(v*2^14))
#define NPMAX  8             // max histogram CTAs per batch
#define HW     262144        // H*W per batch
#define MAXB   64
#define TPB    1024

// scratch (allocation-free rule: __device__ globals; zero-initialized)
__device__ unsigned int       g_part[MAXB * NPMAX * KB];  // packed partials
__device__ int                g_arrive[MAXB];             // per-batch arrival counters
__device__ int                g_done;                     // finished-batch counter
__device__ unsigned long long g_accum;                    // exact integer total

// packed word: T = d*2^22 + S,  S = sum(+-round(v*2^14)) clamped to [0,16383]
__device__ __forceinline__ int decD(unsigned int t) {
    return ((int)t + (1 << 21)) >> 22;
}
__device__ __forceinline__ unsigned int quantS(float v) {
    int S = __float2int_rn(v * 16384.0f);
    return (unsigned int)min(S, 16383);
}

// ---------------------------------------------------------------------------
// Fused kernel, balanced grid: grid = 2*numSM CTAs total, batches split into
// {base, base+1} parts. Last-arriving CTA of a batch scans that batch.
// ---------------------------------------------------------------------------
__global__ void __launch_bounds__(TPB, 2) k_fused(const float* __restrict__ x,
                                                  const float* __restrict__ y,
                                                  float* __restrict__ out,
                                                  int B, int base, int rem) {
    __shared__ unsigned int sh[KB];
    __shared__ int s_last;
    __shared__ int wt[32];
    __shared__ long long wr[32];

    // ---- cta -> (batch b, part q of p, ctaBase) ----
    int cta = blockIdx.x;
    int b, q, p, ctaBase;
    int thr = rem * (base + 1);
    if (cta < thr) {
        b = cta / (base + 1);
        ctaBase = b * (base + 1);
        q = cta - ctaBase;
        p = base + 1;
    } else {
        int r = cta - thr;
        int bb = r / base;
        b = rem + bb;
        ctaBase = thr + bb * base;
        q = r - bb * base;
        p = base;
    }

    int t = threadIdx.x, lane = t & 31, wid = t >> 5;

    uint4* s4 = (uint4*)sh;
    for (int i = t; i < KB / 4; i += TPB) s4[i] = make_uint4(0u, 0u, 0u, 0u);
    __syncthreads();

    // ---- phase 1: packed signed histogram over this part's index range ----
    const int NF4 = HW / 4;  // float4 count per stream per batch
    int i0 = (int)(((long long)NF4 * q) / p);
    int i1 = (int)(((long long)NF4 * (q + 1)) / p);
    const float4* px = (const float4*)(x + (size_t)b * HW);
    const float4* py = (const float4*)(y + (size_t)b * HW);
    for (int i = i0 + t; i < i1; i += TPB) {
        float4 vx = px[i];
        float4 vy = py[i];
        unsigned int s;
        s = quantS(vx.x); atomicAdd(&sh[s >> 1], (1u << 22) + s);
        s = quantS(vy.x); atomicAdd(&sh[s >> 1], (unsigned int)(-(int)((1u << 22) + s)));
        s = quantS(vx.y); atomicAdd(&sh[s >> 1], (1u << 22) + s);
        s = quantS(vy.y); atomicAdd(&sh[s >> 1], (unsigned int)(-(int)((1u << 22) + s)));
        s = quantS(vx.z); atomicAdd(&sh[s >> 1], (1u << 22) + s);
        s = quantS(vy.z); atomicAdd(&sh[s >> 1], (unsigned int)(-(int)((1u << 22) + s)));
        s = quantS(vx.w); atomicAdd(&sh[s >> 1], (1u << 22) + s);
        s = quantS(vy.w); atomicAdd(&sh[s >> 1], (unsigned int)(-(int)((1u << 22) + s)));
    }
    __syncthreads();

    // ---- write partials (coalesced uint4) ----
    {
        uint4* g4 = (uint4*)(g_part + (size_t)cta * KB);
        g4[t] = s4[t];
        g4[t + TPB] = s4[t + TPB];
    }
    __threadfence();

    // ---- arrival: last CTA of this batch becomes the scanner ----
    if (t == 0) {
        int r = atomicAdd(&g_arrive[b], 1);
        s_last = (r == p - 1);
        if (s_last) g_arrive[b] = 0;  // reset for next graph replay
    }
    __syncthreads();
    if (!s_last) return;

    // ---- phase 2: scan this batch's 8192 combined bins (8 per thread) ----
    const unsigned int* pbase = g_part + (size_t)ctaBase * KB;
    int g0 = t * 8;
    unsigned int T[8];
#pragma unroll
    for (int j = 0; j < 8; ++j) T[j] = 0u;
    for (int part = 0; part < p; ++part) {
        const unsigned int* pp = pbase + (size_t)part * KB + g0;
        uint4 a0 = *(const uint4*)(pp);
        uint4 a1 = *(const uint4*)(pp + 4);
        T[0] += a0.x; T[1] += a0.y; T[2] += a0.z; T[3] += a0.w;
        T[4] += a1.x; T[5] += a1.y; T[6] += a1.z; T[7] += a1.w;
    }
    int d[8], S[8];
#pragma unroll
    for (int j = 0; j < 8; ++j) {
        d[j] = decD(T[j]);
        S[j] = (int)T[j] - (d[j] << 22);
    }
    int tsum = 0;
#pragma unroll
    for (int j = 0; j < 8; ++j) tsum += d[j];

    // block exclusive scan of tsum over 1024 threads
    int s = tsum;
#pragma unroll
    for (int o = 1; o < 32; o <<= 1) {
        int u = __shfl_up_sync(0xffffffffu, s, o);
        if (lane >= o) s += u;
    }
    if (lane == 31) wt[wid] = s;
    __syncthreads();
    if (wid == 0) {
        int w = wt[lane];
#pragma unroll
        for (int o = 1; o < 32; o <<= 1) {
            int u = __shfl_up_sync(0xffffffffu, w, o);
            if (lane >= o) w += u;
        }
        wt[lane] = w;
    }
    __syncthreads();
    long long Din = (long long)(wid ? wt[wid - 1] : 0) + (s - tsum);

    // exact per-bin integral: 2^15 * integ_k = 4*Din + d_k*(4k+3) - 2*S_k
    long long acc = 0;
#pragma unroll
    for (int j = 0; j < 8; ++j) {
        long long v = 4 * Din + (long long)d[j] * (4LL * (g0 + j) + 3) - 2LL * S[j];
        acc += v < 0 ? -v : v;
        Din += d[j];
    }

    // block reduce acc (int64)
#pragma unroll
    for (int o = 16; o; o >>= 1) acc += __shfl_down_sync(0xffffffffu, acc, o);
    if (lane == 0) wr[wid] = acc;
    __syncthreads();
    if (wid == 0) {
        acc = wr[lane];
#pragma unroll
        for (int o = 16; o; o >>= 1) acc += __shfl_down_sync(0xffffffffu, acc, o);
        if (lane == 0) {
            atomicAdd(&g_accum, (unsigned long long)acc);
            __threadfence();
            int r2 = atomicAdd(&g_done, 1);
            if (r2 == B - 1) {
                unsigned long long tot = atomicAdd(&g_accum, 0ull);
                out[0] = (float)((double)(long long)tot * (1.0 / 32768.0));
                g_accum = 0ull;  // reset for next graph replay
                g_done = 0;
            }
        }
    }
}

extern "C" void kernel_launch(void* const* d_in, const int* in_sizes, int n_in,
                              void* d_out, int out_size) {
    const float* x = (const float*)d_in[0];
    const float* y = (const float*)d_in[1];
    int B = in_sizes[0] / HW;
    if (B > MAXB) B = MAXB;

    int sm = 148;
    cudaDeviceGetAttribute(&sm, cudaDevAttrMultiProcessorCount, 0);
    int target = 2 * sm;                 // one full wave at occupancy 2
    int base = target / B;
    if (base < 1) base = 1;
    if (base >= NPMAX) { base = NPMAX - 1; }
    int rem = target - base * B;
    if (rem < 0) rem = 0;
    if (rem > B) rem = B;                // (base+1) parts for 'rem' batches
    int grid = base * B + rem;

    k_fused<<<grid, TPB>>>(x, y, (float*)d_out, B, base, rem);
}

// round 8
// speedup vs baseline: 1.1417x; 1.1417x over previous
#include <cuda_runtime.h>
#include <cstdint>

#define KB    8192           // bins (bin = S>>1, S = round(v*2^14))
#define SEG   2048           // bins per CTA in phase 2 (KB / CLUSTER)
#define CLU   4              // CTAs per batch = cluster size
#define HW    262144         // H*W per batch
#define MAXB  64
#define TPB   1024

// scratch (allocation-free rule: __device__ globals; zero-initialized)
__device__ unsigned long long g_accum;   // exact integer total
__device__ int                g_done;    // finished-CTA counter

// packed word: T = d*2^22 + S,  S = sum(+-round(v*2^14)) clamped to [0,16383]
__device__ __forceinline__ int decD(unsigned int t) {
    return ((int)t + (1 << 21)) >> 22;
}
__device__ __forceinline__ unsigned int quantS(float v) {
    int S = __float2int_rn(v * 16384.0f);
    return (unsigned int)min(S, 16383);
}

__device__ __forceinline__ uint32_t smem_u32(const void* p) {
    uint32_t a;
    asm("{ .reg .u64 t; cvta.to.shared.u64 t, %1; cvt.u32.u64 %0, t; }" : "=r"(a) : "l"(p));
    return a;
}
__device__ __forceinline__ uint32_t mapa_u32(uint32_t addr, uint32_t rank) {
    uint32_t r;
    asm volatile("mapa.shared::cluster.u32 %0, %1, %2;" : "=r"(r) : "r"(addr), "r"(rank));
    return r;
}
__device__ __forceinline__ uint2 dsmem_ld2(uint32_t addr) {
    uint2 v;
    asm volatile("ld.shared::cluster.v2.u32 {%0, %1}, [%2];"
                 : "=r"(v.x), "=r"(v.y) : "r"(addr));
    return v;
}
__device__ __forceinline__ int dsmem_ld1(uint32_t addr) {
    int v;
    asm volatile("ld.shared::cluster.u32 %0, [%1];" : "=r"(v) : "r"(addr));
    return v;
}

// ---------------------------------------------------------------------------
// Fused kernel: per-quarter histogram + in-cluster DSMEM combine/scan.
// grid = CLU*B, cluster = 4, block = 1024.
// ---------------------------------------------------------------------------
__global__ void __launch_bounds__(TPB, 2) __cluster_dims__(CLU, 1, 1)
k_fused(const float* __restrict__ x, const float* __restrict__ y,
        float* __restrict__ out, int grid) {
    __shared__ unsigned int sh[KB];
    __shared__ int wt[32];
    __shared__ long long wr[32];
    __shared__ int s_segtot;

    int cta = blockIdx.x;
    int b = cta >> 2, q = cta & 3;
    int t = threadIdx.x, lane = t & 31, wid = t >> 5;

    uint4* s4 = (uint4*)sh;
    for (int i = t; i < KB / 4; i += TPB) s4[i] = make_uint4(0u, 0u, 0u, 0u);
    __syncthreads();

    // ---- phase 1: packed signed histogram over this CTA's quarter ----
    const int QE = HW / CLU;  // 65536 elements each of x, y
    const float4* px = (const float4*)(x + (size_t)b * HW + (size_t)q * QE);
    const float4* py = (const float4*)(y + (size_t)b * HW + (size_t)q * QE);
    for (int i = t; i < QE / 4; i += TPB) {
        float4 vx = px[i];
        float4 vy = py[i];
        unsigned int s;
        s = quantS(vx.x); atomicAdd(&sh[s >> 1], (1u << 22) + s);
        s = quantS(vy.x); atomicAdd(&sh[s >> 1], (unsigned int)(-(int)((1u << 22) + s)));
        s = quantS(vx.y); atomicAdd(&sh[s >> 1], (1u << 22) + s);
        s = quantS(vy.y); atomicAdd(&sh[s >> 1], (unsigned int)(-(int)((1u << 22) + s)));
        s = quantS(vx.z); atomicAdd(&sh[s >> 1], (1u << 22) + s);
        s = quantS(vy.z); atomicAdd(&sh[s >> 1], (unsigned int)(-(int)((1u << 22) + s)));
        s = quantS(vx.w); atomicAdd(&sh[s >> 1], (1u << 22) + s);
        s = quantS(vy.w); atomicAdd(&sh[s >> 1], (unsigned int)(-(int)((1u << 22) + s)));
    }
    __syncthreads();

    // ---- cluster sync #1: all 4 histograms of this batch are complete ----
    asm volatile("barrier.cluster.arrive.aligned;" ::: "memory");
    asm volatile("barrier.cluster.wait.aligned;" ::: "memory");

    // ---- phase 2: combine my 2048-bin segment across the 4 peers (DSMEM) ----
    // thread t handles bins k0 = q*SEG + 2*t, k0+1
    uint32_t myaddr = smem_u32(sh) + (uint32_t)(q * SEG + 2 * t) * 4u;
    unsigned int T0 = 0u, T1 = 0u;
#pragma unroll
    for (int r = 0; r < CLU; ++r) {
        uint2 v = dsmem_ld2(mapa_u32(myaddr, (uint32_t)r));
        T0 += v.x;
        T1 += v.y;
    }
    int d0 = decD(T0), d1 = decD(T1);
    int S0 = (int)T0 - (d0 << 22);
    int S1 = (int)T1 - (d1 << 22);
    int tsum = d0 + d1;

    // block exclusive scan of tsum over 1024 threads
    int s = tsum;
#pragma unroll
    for (int o = 1; o < 32; o <<= 1) {
        int u = __shfl_up_sync(0xffffffffu, s, o);
        if (lane >= o) s += u;
    }
    if (lane == 31) wt[wid] = s;
    __syncthreads();
    if (wid == 0) {
        int w = wt[lane];
#pragma unroll
        for (int o = 1; o < 32; o <<= 1) {
            int u = __shfl_up_sync(0xffffffffu, w, o);
            if (lane >= o) w += u;
        }
        wt[lane] = w;
    }
    __syncthreads();
    int excl = (wid ? wt[wid - 1] : 0) + (s - tsum);
    if (t == 0) s_segtot = wt[31];   // my segment's total d
    __syncthreads();

    // ---- cluster sync #2: segment totals visible cluster-wide ----
    asm volatile("barrier.cluster.arrive.aligned;" ::: "memory");
    asm volatile("barrier.cluster.wait.aligned;" ::: "memory");

    // carry into my segment = sum of earlier segments' totals
    uint32_t segaddr = smem_u32(&s_segtot);
    int carry = 0;
#pragma unroll
    for (int r = 0; r < CLU; ++r)
        if (r < q) carry += dsmem_ld1(mapa_u32(segaddr, (uint32_t)r));

    long long Din = (long long)carry + excl;
    int k0 = q * SEG + 2 * t;  // global bin index of first of my 2 bins

    // exact per-bin integral: 2^15 * integ_k = 4*Din + d_k*(4k+3) - 2*S_k
    long long acc, v;
    v = 4 * Din + (long long)d0 * (4LL * k0 + 3) - 2LL * S0;
    acc = v < 0 ? -v : v;
    Din += d0;
    v = 4 * Din + (long long)d1 * (4LL * k0 + 7) - 2LL * S1;
    acc += v < 0 ? -v : v;

    // block reduce acc (int64)
#pragma unroll
    for (int o = 16; o; o >>= 1) acc += __shfl_down_sync(0xffffffffu, acc, o);
    if (lane == 0) wr[wid] = acc;
    __syncthreads();
    if (wid == 0) {
        acc = wr[lane];
#pragma unroll
        for (int o = 16; o; o >>= 1) acc += __shfl_down_sync(0xffffffffu, acc, o);
        if (lane == 0) {
            atomicAdd(&g_accum, (unsigned long long)acc);
            int r2 = atomicAdd(&g_done, 1);
            if (r2 == grid - 1) {
                unsigned long long tot = atomicAdd(&g_accum, 0ull);
                out[0] = (float)((double)(long long)tot * (1.0 / 32768.0));
                g_accum = 0ull;  // reset for next graph replay
                g_done = 0;
            }
        }
    }
}

extern "C" void kernel_launch(void* const* d_in, const int* in_sizes, int n_in,
                              void* d_out, int out_size) {
    const float* x = (const float*)d_in[0];
    const float* y = (const float*)d_in[1];
    int B = in_sizes[0] / HW;
    if (B > MAXB) B = MAXB;
    int grid = CLU * B;

    k_fused<<<grid, TPB>>>(x, y, (float*)d_out, grid);
}